// round 1
// baseline (speedup 1.0000x reference)
#include <cuda_runtime.h>
#include <math_constants.h>

#define T_LEN 8192
#define B_SZ  256
#define E_CH  8
#define KS    15
#define TILE_A 2048
#define TD    1024
#define TPI_F 6.28318530717958647692f

// ---------------------------------------------------------------------------
// Kernel A: fused per-channel dilated conv pair -> latent (B,E,T)
// grid: B*E*(T/TILE_A) blocks, 256 threads
// ---------------------------------------------------------------------------
__global__ __launch_bounds__(256) void latent_kernel(
    const float* __restrict__ x,
    const float* __restrict__ W1, const float* __restrict__ b1,
    const float* __restrict__ W2, const float* __restrict__ b2,
    float* __restrict__ latent)
{
    extern __shared__ float sm[];
    const int blk  = blockIdx.x;
    const int tile = blk & 3;           // T/TILE_A = 4
    const int be   = blk >> 2;
    const int e    = be & 7;
    const int b    = be >> 3;
    const int d    = 1 << e;            // dilation
    const int t0   = tile * TILE_A;

    float* sx = sm;                             // TILE_A + 28*128 floats max
    float* sh = sm + (TILE_A + 28 * 128);       // 2 rows of (TILE_A + 14*128)
    const int HLmax = TILE_A + 14 * 128;
    const int XL = TILE_A + 28 * d;
    const int HL = TILE_A + 14 * d;
    const int xs = t0 - 14 * d;
    const int hs = t0 - 7 * d;

    const float* xrow = x + (size_t)b * T_LEN;
    for (int i = threadIdx.x; i < XL; i += blockDim.x) {
        int g = xs + i;
        sx[i] = (g >= 0 && g < T_LEN) ? xrow[g] : 0.f;
    }

    float w1a[KS], w1b[KS], w2a[KS], w2b[KS];
#pragma unroll
    for (int j = 0; j < KS; j++) {
        w1a[j] = W1[(e * 2 + 0) * KS + j];
        w1b[j] = W1[(e * 2 + 1) * KS + j];
        w2a[j] = W2[(e * 2 + 0) * KS + j];
        w2b[j] = W2[(e * 2 + 1) * KS + j];
    }
    const float bb1a = b1[e * 2], bb1b = b1[e * 2 + 1], bb2 = b2[e];
    __syncthreads();

    for (int i = threadIdx.x; i < HL; i += blockDim.x) {
        int g = hs + i;
        float h0 = 0.f, h1 = 0.f;
        if (g >= 0 && g < T_LEN) {
            h0 = bb1a; h1 = bb1b;
#pragma unroll
            for (int j = 0; j < KS; j++) {
                float xv = sx[i + j * d];
                h0 += w1a[j] * xv;
                h1 += w1b[j] * xv;
            }
        }
        sh[i] = h0;
        sh[HLmax + i] = h1;
    }
    __syncthreads();

    float* lrow = latent + (size_t)be * T_LEN + t0;
    for (int i = threadIdx.x; i < TILE_A; i += blockDim.x) {
        float acc = bb2;
#pragma unroll
        for (int k = 0; k < KS; k++) {
            acc += w2a[k] * sh[i + k * d] + w2b[k] * sh[HLmax + i + k * d];
        }
        lrow[i] = acc;
    }
}

// ---------------------------------------------------------------------------
// Kernel B: per-(b,e) row — fc dots, real FFT (length 8192 via complex 4096),
// spectral reductions, scalar outputs p/f/a/b_off.
// grid: B*E blocks, 512 threads
// ---------------------------------------------------------------------------
__global__ __launch_bounds__(512) void fft_kernel(
    const float* __restrict__ latent,
    const float* __restrict__ fcW, const float* __restrict__ fcb,
    float* __restrict__ pOut, float* __restrict__ fOut,
    float* __restrict__ aOut, float* __restrict__ bOut)
{
    const int M = 4096;                 // complex FFT length
    extern __shared__ float smf[];
    float2* bufA = (float2*)smf;        // 4096
    float2* bufB = bufA + M;            // 4096
    float2* tw   = bufB + M;            // 2048 twiddles
    __shared__ double red[64];

    const int be = blockIdx.x;
    const int e  = be & 7;
    const int tid = threadIdx.x;

    const float2* rowc = (const float2*)(latent + (size_t)be * T_LEN);
    const float2* fw0  = (const float2*)(fcW + (size_t)(e * 2 + 0) * T_LEN);
    const float2* fw1  = (const float2*)(fcW + (size_t)(e * 2 + 1) * T_LEN);

    double v0 = 0.0, v1 = 0.0;
    for (int i = tid; i < M; i += blockDim.x) {
        float2 z = rowc[i];
        bufA[i] = z;
        float2 a0 = fw0[i], a1 = fw1[i];
        v0 += (double)(z.x * a0.x + z.y * a0.y);
        v1 += (double)(z.x * a1.x + z.y * a1.y);
    }
    for (int i = tid; i < 2048; i += blockDim.x) {
        float s, c;
        sincosf(-(float)CUDART_PI * (float)i / 2048.0f, &s, &c);
        tw[i] = make_float2(c, s);
    }
    __syncthreads();

    // Stockham autosort radix-2, 12 stages
    float2* bin  = bufA;
    float2* bout = bufB;
    const int l = M / 2;
    for (int s = 0; s < 12; s++) {
        const int m = 1 << s;
        for (int idx = tid; idx < l; idx += blockDim.x) {
            int r  = idx & (m - 1);
            int qm = idx - r;                // q*m
            float2 u = bin[idx];
            float2 v = bin[idx + l];
            float2 w = tw[r << (11 - s)];
            float2 t = make_float2(w.x * v.x - w.y * v.y,
                                   w.x * v.y + w.y * v.x);
            int o = (qm << 1) + r;
            bout[o]     = make_float2(u.x + t.x, u.y + t.y);
            bout[o + m] = make_float2(u.x - t.x, u.y - t.y);
        }
        __syncthreads();
        float2* tmp = bin; bin = bout; bout = tmp;
    }
    // bin now holds Z_k in natural order

    double psum = 0.0, wsum = 0.0;
    for (int k = tid + 1; k < M; k += blockDim.x) {
        float2 zk = bin[k];
        float2 zm = bin[M - k];
        float Ax = 0.5f * (zk.x + zm.x), Ay = 0.5f * (zk.y - zm.y);
        float Bx = 0.5f * (zk.x - zm.x), By = 0.5f * (zk.y + zm.y);
        float s, c;
        __sincosf(-(float)CUDART_PI * (float)k / (float)M, &s, &c);
        // X = A + W * (-i*B), W = (c, s), -i*B = (By, -Bx)
        float Xr = Ax + c * By + s * Bx;
        float Xi = Ay - c * Bx + s * By;
        float pw = Xr * Xr + Xi * Xi;
        psum += (double)pw;
        wsum += (double)k * (double)pw;
    }
    if (tid == 0) {
        float xm = bin[0].x - bin[0].y;   // Nyquist bin (real)
        psum += (double)(xm * xm);
        wsum += (double)M * (double)(xm * xm);
    }

    // block reduction of 4 doubles
    const unsigned mask = 0xffffffffu;
#pragma unroll
    for (int o = 16; o > 0; o >>= 1) {
        psum += __shfl_down_sync(mask, psum, o);
        wsum += __shfl_down_sync(mask, wsum, o);
        v0   += __shfl_down_sync(mask, v0, o);
        v1   += __shfl_down_sync(mask, v1, o);
    }
    const int warp = tid >> 5, lane = tid & 31;
    if (lane == 0) {
        red[warp] = psum; red[16 + warp] = wsum;
        red[32 + warp] = v0; red[48 + warp] = v1;
    }
    __syncthreads();
    if (tid == 0) {
        double P = 0, Wm = 0, V0 = 0, V1 = 0;
        for (int i = 0; i < 16; i++) {
            P += red[i]; Wm += red[16 + i]; V0 += red[32 + i]; V1 += red[48 + i];
        }
        V0 += (double)fcb[e * 2];
        V1 += (double)fcb[e * 2 + 1];
        float f    = (float)(0.5 * Wm / P);
        float a    = 2.0f * sqrtf((float)P) / (float)T_LEN;
        float boff = (bin[0].x + bin[0].y) / (float)T_LEN;
        float p    = atan2f((float)V1, (float)V0) / TPI_F;
        pOut[be] = p; fOut[be] = f; aOut[be] = a; bOut[be] = boff;
    }
}

// ---------------------------------------------------------------------------
// Kernel D: sinusoid resynthesis (sig) + fused 3-level grouped deconv tree.
// grid: B*(T/TD) blocks, 256 threads
// ---------------------------------------------------------------------------
__global__ __launch_bounds__(256) void sig_tree_kernel(
    const float* __restrict__ pArr, const float* __restrict__ fArr,
    const float* __restrict__ aArr, const float* __restrict__ bArr,
    const float* __restrict__ dW0, const float* __restrict__ db0,
    const float* __restrict__ dW1, const float* __restrict__ db1,
    const float* __restrict__ dW2, const float* __restrict__ db2,
    float* __restrict__ sig, float* __restrict__ outp)
{
    extern __shared__ float smd[];
    const int SW  = TD + 42;   // sig row width (halo 21 each side)
    const int W0L = TD + 28;   // y0 row width
    const int W1L = TD + 14;   // y1 row width
    float* ssig = smd;                  // 8 * SW
    float* sy0  = ssig + 8 * SW;        // 4 * W0L
    float* sy1  = sy0 + 4 * W0L;        // 2 * W1L
    __shared__ float sca[8], scf[8], scp[8], scb[8];
    __shared__ float sdw0[8 * KS], sdw1[4 * KS], sdw2[2 * KS];
    __shared__ float sdb0[4], sdb1[2], sdb2[1];

    const int blk  = blockIdx.x;
    const int tile = blk & 7;          // T/TD = 8
    const int b    = blk >> 3;
    const int t0   = tile * TD;
    const int tid  = threadIdx.x;

    if (tid < 8) {
        sca[tid] = aArr[b * 8 + tid]; scf[tid] = fArr[b * 8 + tid];
        scp[tid] = pArr[b * 8 + tid]; scb[tid] = bArr[b * 8 + tid];
    }
    if (tid < 8 * KS) sdw0[tid] = dW0[tid];
    if (tid < 4 * KS) sdw1[tid] = dW1[tid];
    if (tid < 2 * KS) sdw2[tid] = dW2[tid];
    if (tid < 4) sdb0[tid] = db0[tid];
    if (tid < 2) sdb1[tid] = db1[tid];
    if (tid == 0) sdb2[0] = db2[0];
    __syncthreads();

    const float inv = 2.0f / (float)(T_LEN - 1);
    for (int i = tid; i < 8 * SW; i += blockDim.x) {
        int e = i / SW, j = i - e * SW;
        int t = t0 - 21 + j;
        float val = 0.f;
        if (t >= 0 && t < T_LEN) {
            float arg = -1.0f + (float)t * inv;
            val = sca[e] * sinf(TPI_F * (scf[e] * arg + scp[e])) + scb[e];
            if (t >= t0 && t < t0 + TD)
                sig[((size_t)b * 8 + e) * T_LEN + t] = val;
        }
        ssig[i] = val;
    }
    __syncthreads();

    for (int i = tid; i < 4 * W0L; i += blockDim.x) {
        int g = i / W0L, j = i - g * W0L;
        int t = t0 - 14 + j;
        float acc = 0.f;
        if (t >= 0 && t < T_LEN) {
            acc = sdb0[g];
            const float* s0 = ssig + (2 * g) * SW + j;
            const float* s1 = ssig + (2 * g + 1) * SW + j;
#pragma unroll
            for (int k = 0; k < KS; k++)
                acc += sdw0[(2 * g) * KS + k] * s0[k]
                     + sdw0[(2 * g + 1) * KS + k] * s1[k];
        }
        sy0[i] = acc;
    }
    __syncthreads();

    for (int i = tid; i < 2 * W1L; i += blockDim.x) {
        int g = i / W1L, j = i - g * W1L;
        int t = t0 - 7 + j;
        float acc = 0.f;
        if (t >= 0 && t < T_LEN) {
            acc = sdb1[g];
            const float* s0 = sy0 + (2 * g) * W0L + j;
            const float* s1 = sy0 + (2 * g + 1) * W0L + j;
#pragma unroll
            for (int k = 0; k < KS; k++)
                acc += sdw1[(2 * g) * KS + k] * s0[k]
                     + sdw1[(2 * g + 1) * KS + k] * s1[k];
        }
        sy1[i] = acc;
    }
    __syncthreads();

    for (int j = tid; j < TD; j += blockDim.x) {
        float acc = sdb2[0];
        const float* s0 = sy1 + j;
        const float* s1 = sy1 + W1L + j;
#pragma unroll
        for (int k = 0; k < KS; k++)
            acc += sdw2[k] * s0[k] + sdw2[KS + k] * s1[k];
        outp[(size_t)b * T_LEN + t0 + j] = acc;
    }
}

// ---------------------------------------------------------------------------
extern "C" void kernel_launch(void* const* d_in, const int* in_sizes, int n_in,
                              void* d_out, int out_size)
{
    const float* x   = (const float*)d_in[0];
    const float* W1  = (const float*)d_in[1];
    const float* b1  = (const float*)d_in[2];
    const float* W2  = (const float*)d_in[3];
    const float* b2  = (const float*)d_in[4];
    const float* fcW = (const float*)d_in[5];
    const float* fcb = (const float*)d_in[6];
    const float* dW0 = (const float*)d_in[7];
    const float* db0 = (const float*)d_in[8];
    const float* dW1 = (const float*)d_in[9];
    const float* db1 = (const float*)d_in[10];
    const float* dW2 = (const float*)d_in[11];
    const float* db2 = (const float*)d_in[12];

    float* out = (float*)d_out;
    float* outMain = out;                                        // (B, T)
    float* latent  = out + (size_t)B_SZ * T_LEN;                 // (B, E, T)
    float* sig     = latent + (size_t)B_SZ * E_CH * T_LEN;       // (B, E, T)
    float* pOut    = sig + (size_t)B_SZ * E_CH * T_LEN;          // (B, E, 1)
    float* fOut    = pOut + B_SZ * E_CH;
    float* aOut    = fOut + B_SZ * E_CH;
    float* bOut    = aOut + B_SZ * E_CH;

    const size_t smA = (size_t)(TILE_A + 28 * 128 + 2 * (TILE_A + 14 * 128)) * sizeof(float);
    const size_t smB = (size_t)(4096 + 4096 + 2048) * sizeof(float2);
    const size_t smD = (size_t)(8 * (TD + 42) + 4 * (TD + 28) + 2 * (TD + 14)) * sizeof(float);

    cudaFuncSetAttribute(latent_kernel,  cudaFuncAttributeMaxDynamicSharedMemorySize, (int)smA);
    cudaFuncSetAttribute(fft_kernel,     cudaFuncAttributeMaxDynamicSharedMemorySize, (int)smB);
    cudaFuncSetAttribute(sig_tree_kernel, cudaFuncAttributeMaxDynamicSharedMemorySize, (int)smD);

    latent_kernel<<<B_SZ * E_CH * (T_LEN / TILE_A), 256, smA>>>(x, W1, b1, W2, b2, latent);
    fft_kernel<<<B_SZ * E_CH, 512, smB>>>(latent, fcW, fcb, pOut, fOut, aOut, bOut);
    sig_tree_kernel<<<B_SZ * (T_LEN / TD), 256, smD>>>(pOut, fOut, aOut, bOut,
                                                       dW0, db0, dW1, db1, dW2, db2,
                                                       sig, outMain);
}